// round 15
// baseline (speedup 1.0000x reference)
#include <cuda_runtime.h>
#include <cuda_bf16.h>
#include <math.h>
#include <float.h>
#include <stdint.h>

#define N_NODES 4096
#define IN_DIM  1024
#define OUT_DIM 512
#define NHEADS  4
#define HDIM    128
#define TOPK    16
#define NEG_SLOPE 0.2f

#define GMAXC  1024
#define THRESH 0.98f

#define KC  64              // bf16 per k-chunk (128 B row)
#define NSUPER 16           // 1024 / 64 k-slices; each serves 3 term passes
#define SUPER_BYTES 65536   // Ahi|Alo|Bhi|Blo  (4 x 16 KB)
#define SMEM_DYN (2 * SUPER_BYTES + 1024)

// Scratch (no cudaMalloc allowed)
__device__ float g_Wh[N_NODES * OUT_DIM];                 // 8 MB
__device__ __nv_bfloat16 g_Abf[(size_t)N_NODES * 2048];   // [x_hi | x_lo]  16 MB
__device__ __nv_bfloat16 g_Bbf[(size_t)OUT_DIM * 2048];   // [W_hi | W_lo]   2 MB
__device__ float g_ssrc[N_NODES * NHEADS];
__device__ float g_sdst[N_NODES * NHEADS];
__device__ int   g_topk[N_NODES * TOPK];
__device__ int   g_ccnt[N_NODES];                         // candidate counters
__device__ float g_cval[(size_t)N_NODES * GMAXC];         // 16 MB
__device__ int   g_cidx[(size_t)N_NODES * GMAXC];         // 16 MB

// ---------------------------------------------------------------------------
// helpers
// ---------------------------------------------------------------------------
__device__ __forceinline__ uint32_t smem_to_u32(const void* p) {
    uint32_t a;
    asm("{ .reg .u64 t; cvta.to.shared.u64 t, %1; cvt.u32.u64 %0, t; }"
        : "=r"(a) : "l"(p));
    return a;
}
__device__ __forceinline__ void ldsm4(uint32_t* r, uint32_t addr) {
    asm volatile("ldmatrix.sync.aligned.m8n8.x4.shared.b16 {%0,%1,%2,%3}, [%4];"
        : "=r"(r[0]), "=r"(r[1]), "=r"(r[2]), "=r"(r[3]) : "r"(addr));
}
__device__ __forceinline__ void mma16816(float* d, const uint32_t* a,
                                         uint32_t b0, uint32_t b1) {
    asm volatile("mma.sync.aligned.m16n8k16.row.col.f32.bf16.bf16.f32 "
        "{%0,%1,%2,%3}, {%4,%5,%6,%7}, {%8,%9}, {%0,%1,%2,%3};"
        : "+f"(d[0]), "+f"(d[1]), "+f"(d[2]), "+f"(d[3])
        : "r"(a[0]), "r"(a[1]), "r"(a[2]), "r"(a[3]), "r"(b0), "r"(b1));
}
__device__ __forceinline__ void cpasync16(uint32_t sdst, const void* gsrc) {
    asm volatile("cp.async.cg.shared.global [%0], [%1], 16;"
        :: "r"(sdst), "l"(gsrc));
}
__device__ __forceinline__ void cpasync_commit() {
    asm volatile("cp.async.commit_group;");
}
__device__ __forceinline__ void cpasync_wait1() {
    asm volatile("cp.async.wait_group 1;");
}

// ---------------------------------------------------------------------------
// fp32 -> (hi, lo) bf16 split conversion
// ---------------------------------------------------------------------------
__device__ __forceinline__ void split4(float4 v, uint2& hi, uint2& lo) {
    __nv_bfloat16 hx = __float2bfloat16_rn(v.x), hy = __float2bfloat16_rn(v.y);
    __nv_bfloat16 hz = __float2bfloat16_rn(v.z), hw = __float2bfloat16_rn(v.w);
    float lx = v.x - __bfloat162float(hx), ly = v.y - __bfloat162float(hy);
    float lz = v.z - __bfloat162float(hz), lw = v.w - __bfloat162float(hw);
    __nv_bfloat162 h01 = __halves2bfloat162(hx, hy);
    __nv_bfloat162 h23 = __halves2bfloat162(hz, hw);
    __nv_bfloat162 l01 = __floats2bfloat162_rn(lx, ly);
    __nv_bfloat162 l23 = __floats2bfloat162_rn(lz, lw);
    hi.x = *reinterpret_cast<uint32_t*>(&h01); hi.y = *reinterpret_cast<uint32_t*>(&h23);
    lo.x = *reinterpret_cast<uint32_t*>(&l01); lo.y = *reinterpret_cast<uint32_t*>(&l23);
}

// Merged conversion: blocks [0,4096) handle x -> g_Abf, [4096,4608) W -> g_Bbf.
__global__ __launch_bounds__(256) void conv_xw_kernel(const float* __restrict__ x,
                                                      const float* __restrict__ W) {
    const bool isW = blockIdx.x >= 4096;
    const int blk  = isW ? (blockIdx.x - 4096) : blockIdx.x;
    const float* src = isW ? W : x;
    __nv_bfloat16* dst = isW ? g_Bbf : g_Abf;

    int i = blk * 256 + threadIdx.x;             // float4 index
    float4 v = reinterpret_cast<const float4*>(src)[i];
    int r = i >> 8, c4 = i & 255;
    uint2 hi, lo; split4(v, hi, lo);
    __nv_bfloat16* base = dst + (size_t)r * 2048 + c4 * 4;
    *reinterpret_cast<uint2*>(base)        = hi;
    *reinterpret_cast<uint2*>(base + 1024) = lo;
}

// ---------------------------------------------------------------------------
// HMMA GEMM + fused score. 512 threads / 16 warps, warp tile 32x32,
// 128x128 CTA tile. Term-reuse super-chunks with A-FRAG REUSE:
// pass order hi*hi -> hi*lo (Ahi frags kept) -> lo*hi. 40 ldsm/super/warp.
// NBUF=2, prefetch depth 1. CTA column == head; score in-CTA.
// ---------------------------------------------------------------------------
__global__ __launch_bounds__(512, 1) void hmma_gemm_kernel(const float* __restrict__ a) {
    extern __shared__ char smem_raw[];
    char* sm = (char*)(((uintptr_t)smem_raw + 1023) & ~(uintptr_t)1023);
    const uint32_t sb = smem_to_u32(sm);
    __shared__ float sa[2 * HDIM];     // a_src | a_dst
    __shared__ float ssum[2 * 128];    // per-row src | dst partials

    const int tid  = threadIdx.x;
    const int wid  = tid >> 5;
    const int lane = tid & 31;
    const int bm = blockIdx.y * 128;
    const int bn = blockIdx.x * 128;
    const int m0w = (wid & 3) * 32;    // warp m origin
    const int n0w = (wid >> 2) * 32;   // warp n origin

    if (tid < 2 * HDIM) sa[tid] = a[tid];

    // loader mapping: 512 threads cover 128 rows x 128 B; 2 x 16 B per tile
    const int row  = tid >> 2;
    const int quar = tid & 3;          // 32-byte chunk within row
    const __nv_bfloat16* gA = g_Abf + (size_t)(bm + row) * 2048 + quar * 16;
    const __nv_bfloat16* gB = g_Bbf + (size_t)(bn + row) * 2048 + quar * 16;
    const uint32_t strow = (uint32_t)row * 128;
    const uint32_t stswz = ((uint32_t)row & 7) << 4;

    // ldmatrix per-lane constants (SW128, 128 B rows)
    const uint32_t arow  = lane & 15;
    const uint32_t acolx = (lane & 16) ? 16u : 0u;
    const uint32_t aswz  = (arow & 7) << 4;
    const uint32_t brow  = (lane & 7) + ((lane & 16) >> 1);
    const uint32_t bcolx = (lane & 8) ? 16u : 0u;
    const uint32_t bswz  = (brow & 7) << 4;

    float acc[2][4][4] = {};

    // load super-chunk s: Ahi | Alo | Bhi | Blo into buffer s % 2
    auto issue_super = [&](int s) {
        const int k = s * KC;
        const uint32_t base = sb + (uint32_t)(s & 1) * SUPER_BYTES;
#pragma unroll
        for (int i = 0; i < 2; i++) {
            const uint32_t so = strow + (((uint32_t)(quar * 32 + i * 16)) ^ stswz);
            cpasync16(base + so,         gA + k + i * 8);          // Ahi
            cpasync16(base + 16384 + so, gA + 1024 + k + i * 8);   // Alo
            cpasync16(base + 32768 + so, gB + k + i * 8);          // Bhi
            cpasync16(base + 49152 + so, gB + 1024 + k + i * 8);   // Blo
        }
    };

    // prologue: supers 0 and 1 in flight
    issue_super(0); cpasync_commit();
    issue_super(1); cpasync_commit();

#pragma unroll 1
    for (int s = 0; s < NSUPER; s++) {
        cpasync_wait1();        // super s resident (s+1 may be in flight)
        __syncthreads();

        const uint32_t base = sb + (uint32_t)(s & 1) * SUPER_BYTES;
        uint32_t afr[4][2][4];
        uint32_t bfr[4][2][4];

        auto load_a = [&](uint32_t Ab) {
#pragma unroll
            for (int ks = 0; ks < 4; ks++)
#pragma unroll
                for (int mf = 0; mf < 2; mf++)
                    ldsm4(afr[ks][mf],
                          Ab + (m0w + mf * 16 + arow) * 128 + ((ks * 32 + acolx) ^ aswz));
        };
        auto load_b = [&](uint32_t Bb) {
#pragma unroll
            for (int ks = 0; ks < 4; ks++)
#pragma unroll
                for (int nq = 0; nq < 2; nq++)
                    ldsm4(bfr[ks][nq],
                          Bb + (n0w + nq * 16 + brow) * 128 + ((ks * 32 + bcolx) ^ bswz));
        };
        auto do_mma = [&]() {
#pragma unroll
            for (int ks = 0; ks < 4; ks++)
#pragma unroll
                for (int mf = 0; mf < 2; mf++)
#pragma unroll
                    for (int nf = 0; nf < 4; nf++)
                        mma16816(acc[mf][nf], afr[ks][mf],
                                 bfr[ks][nf >> 1][(nf & 1) * 2],
                                 bfr[ks][nf >> 1][(nf & 1) * 2 + 1]);
        };

        load_a(base);               // Ahi
        load_b(base + 32768);       // Bhi
        do_mma();                   // hi*hi
        load_b(base + 49152);       // Blo (Ahi frags reused)
        do_mma();                   // hi*lo
        load_a(base + 16384);       // Alo
        load_b(base + 32768);       // Bhi
        do_mma();                   // lo*hi

        __syncthreads();            // all warps done reading buffer s&1
        if (s + 2 < NSUPER) issue_super(s + 2);
        cpasync_commit();           // one commit per iter keeps accounting uniform
    }

    // ---- epilogue 1: Wh tile to global ----
#pragma unroll
    for (int mf = 0; mf < 2; mf++) {
        const int r0 = bm + m0w + mf * 16 + (lane >> 2);
#pragma unroll
        for (int nf = 0; nf < 4; nf++) {
            const int c = bn + n0w + nf * 8 + (lane & 3) * 2;
            *reinterpret_cast<float2*>(g_Wh + (size_t)r0 * OUT_DIM + c) =
                make_float2(acc[mf][nf][0], acc[mf][nf][1]);
            *reinterpret_cast<float2*>(g_Wh + (size_t)(r0 + 8) * OUT_DIM + c) =
                make_float2(acc[mf][nf][2], acc[mf][nf][3]);
        }
    }

    // ---- epilogue 2: fused score (CTA owns head h = blockIdx.x) ----
    __syncthreads();
    if (tid < 256) ssum[tid] = 0.f;
    __syncthreads();

    float sp[2][2] = {}, dp[2][2] = {};   // [mf][rowhalf]
#pragma unroll
    for (int nf = 0; nf < 4; nf++) {
        const int c = n0w + nf * 8 + (lane & 3) * 2;   // 0..127 within head
        const float a0s = sa[c],        a1s = sa[c + 1];
        const float a0d = sa[HDIM + c], a1d = sa[HDIM + c + 1];
#pragma unroll
        for (int mf = 0; mf < 2; mf++) {
            sp[mf][0] += acc[mf][nf][0] * a0s + acc[mf][nf][1] * a1s;
            sp[mf][1] += acc[mf][nf][2] * a0s + acc[mf][nf][3] * a1s;
            dp[mf][0] += acc[mf][nf][0] * a0d + acc[mf][nf][1] * a1d;
            dp[mf][1] += acc[mf][nf][2] * a0d + acc[mf][nf][3] * a1d;
        }
    }
#pragma unroll
    for (int o = 1; o <= 2; o <<= 1) {
#pragma unroll
        for (int mf = 0; mf < 2; mf++)
#pragma unroll
            for (int r = 0; r < 2; r++) {
                sp[mf][r] += __shfl_xor_sync(0xffffffffu, sp[mf][r], o);
                dp[mf][r] += __shfl_xor_sync(0xffffffffu, dp[mf][r], o);
            }
    }
    if ((lane & 3) == 0) {
#pragma unroll
        for (int mf = 0; mf < 2; mf++)
#pragma unroll
            for (int r = 0; r < 2; r++) {
                const int rt = m0w + mf * 16 + (lane >> 2) + r * 8;
                atomicAdd(&ssum[rt], sp[mf][r]);
                atomicAdd(&ssum[128 + rt], dp[mf][r]);
            }
    }
    __syncthreads();
    if (tid < 128) {
        const int h = blockIdx.x;
        g_ssrc[(bm + tid) * NHEADS + h] = ssum[tid];
        g_sdst[(bm + tid) * NHEADS + h] = ssum[128 + tid];
    }
}

// ---------------------------------------------------------------------------
// Scan: stream adj, collect candidates >= THRESH to GLOBAL scratch.
// Warp per row, no smem, minimal registers. Grid 512 x 256.
// ---------------------------------------------------------------------------
__global__ __launch_bounds__(256) void scan_kernel(const float* __restrict__ adj) {
    const int w    = threadIdx.x >> 5;
    const int lane = threadIdx.x & 31;
    const int row  = blockIdx.x * 8 + w;
    const float4* r4 = reinterpret_cast<const float4*>(adj + (size_t)row * N_NODES);
    float* cv = g_cval + (size_t)row * GMAXC;
    int*   ci = g_cidx + (size_t)row * GMAXC;

#pragma unroll 1
    for (int base = 0; base < N_NODES / 4; base += 128) {
        float4 v0 = r4[base + lane];
        float4 v1 = r4[base + lane + 32];
        float4 v2 = r4[base + lane + 64];
        float4 v3 = r4[base + lane + 96];
        float m01 = fmaxf(fmaxf(fmaxf(v0.x, v0.y), fmaxf(v0.z, v0.w)),
                          fmaxf(fmaxf(v1.x, v1.y), fmaxf(v1.z, v1.w)));
        float m23 = fmaxf(fmaxf(fmaxf(v2.x, v2.y), fmaxf(v2.z, v2.w)),
                          fmaxf(fmaxf(v3.x, v3.y), fmaxf(v3.z, v3.w)));
        if (m01 >= THRESH) {
#pragma unroll
            for (int q = 0; q < 2; q++) {
                float4 v = q ? v1 : v0;
                const int j0 = (base + lane + q * 32) * 4;
                if (v.x >= THRESH) { int p = atomicAdd(&g_ccnt[row], 1); if (p < GMAXC) { cv[p] = v.x; ci[p] = j0 + 0; } }
                if (v.y >= THRESH) { int p = atomicAdd(&g_ccnt[row], 1); if (p < GMAXC) { cv[p] = v.y; ci[p] = j0 + 1; } }
                if (v.z >= THRESH) { int p = atomicAdd(&g_ccnt[row], 1); if (p < GMAXC) { cv[p] = v.z; ci[p] = j0 + 2; } }
                if (v.w >= THRESH) { int p = atomicAdd(&g_ccnt[row], 1); if (p < GMAXC) { cv[p] = v.w; ci[p] = j0 + 3; } }
            }
        }
        if (m23 >= THRESH) {
#pragma unroll
            for (int q = 2; q < 4; q++) {
                float4 v = (q == 2) ? v2 : v3;
                const int j0 = (base + lane + q * 32) * 4;
                if (v.x >= THRESH) { int p = atomicAdd(&g_ccnt[row], 1); if (p < GMAXC) { cv[p] = v.x; ci[p] = j0 + 0; } }
                if (v.y >= THRESH) { int p = atomicAdd(&g_ccnt[row], 1); if (p < GMAXC) { cv[p] = v.y; ci[p] = j0 + 1; } }
                if (v.z >= THRESH) { int p = atomicAdd(&g_ccnt[row], 1); if (p < GMAXC) { cv[p] = v.z; ci[p] = j0 + 2; } }
                if (v.w >= THRESH) { int p = atomicAdd(&g_ccnt[row], 1); if (p < GMAXC) { cv[p] = v.w; ci[p] = j0 + 3; } }
            }
        }
    }
}

// ---------------------------------------------------------------------------
// Select: top-16 from candidates (or full scan fallback). Warp per row.
// Lexicographic (val desc, idx asc) — matches jax.lax.top_k; order-robust.
// ---------------------------------------------------------------------------
__device__ __forceinline__ void insert16(float (&vals)[TOPK], int (&idxs)[TOPK],
                                         float v, int j) {
    if (v > vals[TOPK - 1] || (v == vals[TOPK - 1] && j < idxs[TOPK - 1])) {
        float pv = FLT_MAX;
        int   pi = -1;
#pragma unroll
        for (int s = 0; s < TOPK; s++) {
            float cv = vals[s];
            int   ci = idxs[s];
            bool gp = (v > pv) || (v == pv && j < pi);
            bool gc = (v > cv) || (v == cv && j < ci);
            vals[s] = gp ? pv : (gc ? v : cv);
            idxs[s] = gp ? pi : (gc ? j : ci);
            pv = cv; pi = ci;
        }
    }
}

__global__ __launch_bounds__(128) void select_kernel(const float* __restrict__ adj) {
    const int w    = threadIdx.x >> 5;
    const int lane = threadIdx.x & 31;
    const int row  = blockIdx.x * 4 + w;
    const int c = g_ccnt[row];

    float vals[TOPK];
    int   idxs[TOPK];
#pragma unroll
    for (int i = 0; i < TOPK; i++) { vals[i] = -FLT_MAX; idxs[i] = 0x7fffffff; }

    if (c >= TOPK && c <= GMAXC) {
        const float* cv = g_cval + (size_t)row * GMAXC;
        const int*   ci = g_cidx + (size_t)row * GMAXC;
        for (int t = lane; t < c; t += 32)
            insert16(vals, idxs, cv[t], ci[t]);
    } else {
        // fallback: exact full scan (arbitrary data safety)
        const float4* r4 = reinterpret_cast<const float4*>(adj + (size_t)row * N_NODES);
        for (int jj = lane; jj < N_NODES / 4; jj += 32) {
            float4 v = r4[jj];
            const int j0 = jj * 4;
            insert16(vals, idxs, v.x, j0 + 0);
            insert16(vals, idxs, v.y, j0 + 1);
            insert16(vals, idxs, v.z, j0 + 2);
            insert16(vals, idxs, v.w, j0 + 3);
        }
    }

#pragma unroll 1
    for (int t = 0; t < TOPK; t++) {
        float bv = vals[0];
        int   bi = idxs[0];
#pragma unroll
        for (int o = 16; o; o >>= 1) {
            float ov = __shfl_xor_sync(0xffffffffu, bv, o);
            int   oi = __shfl_xor_sync(0xffffffffu, bi, o);
            if (ov > bv || (ov == bv && oi < bi)) { bv = ov; bi = oi; }
        }
        const bool win = (idxs[0] == bi) && (vals[0] == bv);
        if (win) {
#pragma unroll
            for (int s = 0; s < TOPK - 1; s++) {
                vals[s] = vals[s + 1];
                idxs[s] = idxs[s + 1];
            }
            vals[TOPK - 1] = -FLT_MAX;
            idxs[TOPK - 1] = 0x7fffffff;
        }
        if (lane == 0) g_topk[row * TOPK + t] = bi;
    }
}

// ---------------------------------------------------------------------------
// Aggregate: PARALLEL softmax + gathered weighted Wh sum + ELU.
// ---------------------------------------------------------------------------
__global__ __launch_bounds__(128) void aggregate_kernel(float* __restrict__ out) {
    const int i   = blockIdx.x;
    const int tid = threadIdx.x;

    __shared__ int   sidx[TOPK];
    __shared__ float salpha[TOPK][NHEADS];

    if (tid < TOPK) sidx[tid] = g_topk[i * TOPK + tid];
    __syncthreads();

    if (tid < TOPK * NHEADS) {
        const int t = tid & 15, h = tid >> 4;
        float e = g_ssrc[i * NHEADS + h] + g_sdst[sidx[t] * NHEADS + h];
        e = (e >= 0.f) ? e : NEG_SLOPE * e;
        float m = e;
#pragma unroll
        for (int o = 8; o; o >>= 1) m = fmaxf(m, __shfl_xor_sync(0xffffffffu, m, o));
        float ex = expf(e - m);
        float s = ex;
#pragma unroll
        for (int o = 8; o; o >>= 1) s += __shfl_xor_sync(0xffffffffu, s, o);
        salpha[t][h] = ex / s;
    }
    __syncthreads();

    const int f = tid;
    const int h = f >> 5;
    float4 acc = make_float4(0.f, 0.f, 0.f, 0.f);
#pragma unroll
    for (int t = 0; t < TOPK; t++) {
        const float4* p = reinterpret_cast<const float4*>(g_Wh + (size_t)sidx[t] * OUT_DIM);
        float4 wv = p[f];
        float al = salpha[t][h];
        acc.x += al * wv.x; acc.y += al * wv.y;
        acc.z += al * wv.z; acc.w += al * wv.w;
    }
    float4 r;
    r.x = (acc.x > 0.f) ? acc.x : expm1f(acc.x);
    r.y = (acc.y > 0.f) ? acc.y : expm1f(acc.y);
    r.z = (acc.z > 0.f) ? acc.z : expm1f(acc.z);
    r.w = (acc.w > 0.f) ? acc.w : expm1f(acc.w);
    reinterpret_cast<float4*>(out + (size_t)i * OUT_DIM)[f] = r;
}

// ---------------------------------------------------------------------------
// Launch: s2 = memset(counters) -> scan -> select (joins before aggregate).
// Main: conv -> gemm(+score) -> aggregate. Select overlaps/trails gemm.
// ---------------------------------------------------------------------------
extern "C" void kernel_launch(void* const* d_in, const int* in_sizes, int n_in,
                              void* d_out, int out_size) {
    const float* x   = (const float*)d_in[0];
    const float* adj = (const float*)d_in[1];
    const float* W   = (const float*)d_in[2];
    const float* a   = (const float*)d_in[3];
    float* out = (float*)d_out;

    static cudaStream_t s2 = nullptr;
    static cudaEvent_t ev_fork = nullptr, ev_topk = nullptr;
    static void* ccnt_addr = nullptr;
    if (s2 == nullptr) {
        cudaStreamCreateWithFlags(&s2, cudaStreamNonBlocking);
        cudaEventCreateWithFlags(&ev_fork, cudaEventDisableTiming);
        cudaEventCreateWithFlags(&ev_topk, cudaEventDisableTiming);
        cudaGetSymbolAddress(&ccnt_addr, g_ccnt);
        cudaFuncSetAttribute(hmma_gemm_kernel,
                             cudaFuncAttributeMaxDynamicSharedMemorySize, SMEM_DYN);
    }

    cudaEventRecord(ev_fork, 0);
    cudaStreamWaitEvent(s2, ev_fork, 0);

    cudaMemsetAsync(ccnt_addr, 0, N_NODES * sizeof(int), s2);
    scan_kernel<<<N_NODES / 8, 256, 0, s2>>>(adj);
    select_kernel<<<N_NODES / 4, 128, 0, s2>>>(adj);
    cudaEventRecord(ev_topk, s2);

    conv_xw_kernel<<<4608, 256>>>(x, W);
    hmma_gemm_kernel<<<dim3(OUT_DIM / 128, N_NODES / 128), 512, SMEM_DYN>>>(a);
    cudaStreamWaitEvent(0, ev_topk, 0);
    aggregate_kernel<<<N_NODES, 128>>>(out);
}

// round 16
// speedup vs baseline: 1.2936x; 1.2936x over previous
#include <cuda_runtime.h>
#include <cuda_bf16.h>
#include <math.h>
#include <float.h>
#include <stdint.h>

#define N_NODES 4096
#define IN_DIM  1024
#define OUT_DIM 512
#define NHEADS  4
#define HDIM    128
#define TOPK    16
#define NEG_SLOPE 0.2f

#define MAXC   192
#define THRESH 0.98f

#define KC  64              // bf16 per k-chunk (128 B row)
#define NSUPER 16           // 1024 / 64 k-slices; each serves 3 term passes
#define SUPER_BYTES 65536   // Ahi|Alo|Bhi|Blo  (4 x 16 KB)
#define SMEM_DYN (2 * SUPER_BYTES + 1024)

// Scratch (no cudaMalloc allowed)
__device__ float g_Wh[N_NODES * OUT_DIM];                 // 8 MB
__device__ __nv_bfloat16 g_Abf[(size_t)N_NODES * 2048];   // [x_hi | x_lo]  16 MB
__device__ __nv_bfloat16 g_Bbf[(size_t)OUT_DIM * 2048];   // [W_hi | W_lo]   2 MB
__device__ float g_ssrc[N_NODES * NHEADS];
__device__ float g_sdst[N_NODES * NHEADS];
__device__ int   g_topk[N_NODES * TOPK];

// ---------------------------------------------------------------------------
// helpers
// ---------------------------------------------------------------------------
__device__ __forceinline__ uint32_t smem_to_u32(const void* p) {
    uint32_t a;
    asm("{ .reg .u64 t; cvta.to.shared.u64 t, %1; cvt.u32.u64 %0, t; }"
        : "=r"(a) : "l"(p));
    return a;
}
__device__ __forceinline__ void ldsm4(uint32_t* r, uint32_t addr) {
    asm volatile("ldmatrix.sync.aligned.m8n8.x4.shared.b16 {%0,%1,%2,%3}, [%4];"
        : "=r"(r[0]), "=r"(r[1]), "=r"(r[2]), "=r"(r[3]) : "r"(addr));
}
__device__ __forceinline__ void mma16816(float* d, const uint32_t* a,
                                         uint32_t b0, uint32_t b1) {
    asm volatile("mma.sync.aligned.m16n8k16.row.col.f32.bf16.bf16.f32 "
        "{%0,%1,%2,%3}, {%4,%5,%6,%7}, {%8,%9}, {%0,%1,%2,%3};"
        : "+f"(d[0]), "+f"(d[1]), "+f"(d[2]), "+f"(d[3])
        : "r"(a[0]), "r"(a[1]), "r"(a[2]), "r"(a[3]), "r"(b0), "r"(b1));
}
__device__ __forceinline__ void cpasync16(uint32_t sdst, const void* gsrc) {
    asm volatile("cp.async.cg.shared.global [%0], [%1], 16;"
        :: "r"(sdst), "l"(gsrc));
}
__device__ __forceinline__ void cpasync_commit() {
    asm volatile("cp.async.commit_group;");
}
__device__ __forceinline__ void cpasync_wait1() {
    asm volatile("cp.async.wait_group 1;");
}

// ---------------------------------------------------------------------------
// fp32 -> (hi, lo) bf16 split conversion
// ---------------------------------------------------------------------------
__device__ __forceinline__ void split4(float4 v, uint2& hi, uint2& lo) {
    __nv_bfloat16 hx = __float2bfloat16_rn(v.x), hy = __float2bfloat16_rn(v.y);
    __nv_bfloat16 hz = __float2bfloat16_rn(v.z), hw = __float2bfloat16_rn(v.w);
    float lx = v.x - __bfloat162float(hx), ly = v.y - __bfloat162float(hy);
    float lz = v.z - __bfloat162float(hz), lw = v.w - __bfloat162float(hw);
    __nv_bfloat162 h01 = __halves2bfloat162(hx, hy);
    __nv_bfloat162 h23 = __halves2bfloat162(hz, hw);
    __nv_bfloat162 l01 = __floats2bfloat162_rn(lx, ly);
    __nv_bfloat162 l23 = __floats2bfloat162_rn(lz, lw);
    hi.x = *reinterpret_cast<uint32_t*>(&h01); hi.y = *reinterpret_cast<uint32_t*>(&h23);
    lo.x = *reinterpret_cast<uint32_t*>(&l01); lo.y = *reinterpret_cast<uint32_t*>(&l23);
}

// Merged conversion: blocks [0,4096) handle x -> g_Abf, [4096,4608) W -> g_Bbf.
__global__ __launch_bounds__(256) void conv_xw_kernel(const float* __restrict__ x,
                                                      const float* __restrict__ W) {
    const bool isW = blockIdx.x >= 4096;
    const int blk  = isW ? (blockIdx.x - 4096) : blockIdx.x;
    const float* src = isW ? W : x;
    __nv_bfloat16* dst = isW ? g_Bbf : g_Abf;

    int i = blk * 256 + threadIdx.x;             // float4 index
    float4 v = reinterpret_cast<const float4*>(src)[i];
    int r = i >> 8, c4 = i & 255;
    uint2 hi, lo; split4(v, hi, lo);
    __nv_bfloat16* base = dst + (size_t)r * 2048 + c4 * 4;
    *reinterpret_cast<uint2*>(base)        = hi;
    *reinterpret_cast<uint2*>(base + 1024) = lo;
}

// ---------------------------------------------------------------------------
// HMMA GEMM + fused score. 512 threads / 16 warps, warp tile 32x32,
// 128x128 CTA tile. Term-reuse super-chunks with A-FRAG REUSE:
// pass order hi*hi -> hi*lo (Ahi frags kept) -> lo*hi. NBUF=2.
// CTA column == head; score reduced in-CTA.
// ---------------------------------------------------------------------------
__global__ __launch_bounds__(512, 1) void hmma_gemm_kernel(const float* __restrict__ a) {
    extern __shared__ char smem_raw[];
    char* sm = (char*)(((uintptr_t)smem_raw + 1023) & ~(uintptr_t)1023);
    const uint32_t sb = smem_to_u32(sm);
    __shared__ float sa[2 * HDIM];     // a_src | a_dst
    __shared__ float ssum[2 * 128];    // per-row src | dst partials

    const int tid  = threadIdx.x;
    const int wid  = tid >> 5;
    const int lane = tid & 31;
    const int bm = blockIdx.y * 128;
    const int bn = blockIdx.x * 128;
    const int m0w = (wid & 3) * 32;    // warp m origin
    const int n0w = (wid >> 2) * 32;   // warp n origin

    if (tid < 2 * HDIM) sa[tid] = a[tid];

    // loader mapping: 512 threads cover 128 rows x 128 B; 2 x 16 B per tile
    const int row  = tid >> 2;
    const int quar = tid & 3;          // 32-byte chunk within row
    const __nv_bfloat16* gA = g_Abf + (size_t)(bm + row) * 2048 + quar * 16;
    const __nv_bfloat16* gB = g_Bbf + (size_t)(bn + row) * 2048 + quar * 16;
    const uint32_t strow = (uint32_t)row * 128;
    const uint32_t stswz = ((uint32_t)row & 7) << 4;

    // ldmatrix per-lane constants (SW128, 128 B rows)
    const uint32_t arow  = lane & 15;
    const uint32_t acolx = (lane & 16) ? 16u : 0u;
    const uint32_t aswz  = (arow & 7) << 4;
    const uint32_t brow  = (lane & 7) + ((lane & 16) >> 1);
    const uint32_t bcolx = (lane & 8) ? 16u : 0u;
    const uint32_t bswz  = (brow & 7) << 4;

    float acc[2][4][4] = {};

    // load super-chunk s: Ahi | Alo | Bhi | Blo into buffer s % 2
    auto issue_super = [&](int s) {
        const int k = s * KC;
        const uint32_t base = sb + (uint32_t)(s & 1) * SUPER_BYTES;
#pragma unroll
        for (int i = 0; i < 2; i++) {
            const uint32_t so = strow + (((uint32_t)(quar * 32 + i * 16)) ^ stswz);
            cpasync16(base + so,         gA + k + i * 8);          // Ahi
            cpasync16(base + 16384 + so, gA + 1024 + k + i * 8);   // Alo
            cpasync16(base + 32768 + so, gB + k + i * 8);          // Bhi
            cpasync16(base + 49152 + so, gB + 1024 + k + i * 8);   // Blo
        }
    };

    // prologue: supers 0 and 1 in flight
    issue_super(0); cpasync_commit();
    issue_super(1); cpasync_commit();

#pragma unroll 1
    for (int s = 0; s < NSUPER; s++) {
        cpasync_wait1();        // super s resident (s+1 may be in flight)
        __syncthreads();

        const uint32_t base = sb + (uint32_t)(s & 1) * SUPER_BYTES;
        uint32_t afr[4][2][4];
        uint32_t bfr[4][2][4];

        auto load_a = [&](uint32_t Ab) {
#pragma unroll
            for (int ks = 0; ks < 4; ks++)
#pragma unroll
                for (int mf = 0; mf < 2; mf++)
                    ldsm4(afr[ks][mf],
                          Ab + (m0w + mf * 16 + arow) * 128 + ((ks * 32 + acolx) ^ aswz));
        };
        auto load_b = [&](uint32_t Bb) {
#pragma unroll
            for (int ks = 0; ks < 4; ks++)
#pragma unroll
                for (int nq = 0; nq < 2; nq++)
                    ldsm4(bfr[ks][nq],
                          Bb + (n0w + nq * 16 + brow) * 128 + ((ks * 32 + bcolx) ^ bswz));
        };
        auto do_mma = [&]() {
#pragma unroll
            for (int ks = 0; ks < 4; ks++)
#pragma unroll
                for (int mf = 0; mf < 2; mf++)
#pragma unroll
                    for (int nf = 0; nf < 4; nf++)
                        mma16816(acc[mf][nf], afr[ks][mf],
                                 bfr[ks][nf >> 1][(nf & 1) * 2],
                                 bfr[ks][nf >> 1][(nf & 1) * 2 + 1]);
        };

        load_a(base);               // Ahi
        load_b(base + 32768);       // Bhi
        do_mma();                   // hi*hi
        load_b(base + 49152);       // Blo (Ahi frags reused)
        do_mma();                   // hi*lo
        load_a(base + 16384);       // Alo
        load_b(base + 32768);       // Bhi
        do_mma();                   // lo*hi

        __syncthreads();            // all warps done reading buffer s&1
        if (s + 2 < NSUPER) issue_super(s + 2);
        cpasync_commit();           // one commit per iter keeps accounting uniform
    }

    // ---- epilogue 1: Wh tile to global ----
#pragma unroll
    for (int mf = 0; mf < 2; mf++) {
        const int r0 = bm + m0w + mf * 16 + (lane >> 2);
#pragma unroll
        for (int nf = 0; nf < 4; nf++) {
            const int c = bn + n0w + nf * 8 + (lane & 3) * 2;
            *reinterpret_cast<float2*>(g_Wh + (size_t)r0 * OUT_DIM + c) =
                make_float2(acc[mf][nf][0], acc[mf][nf][1]);
            *reinterpret_cast<float2*>(g_Wh + (size_t)(r0 + 8) * OUT_DIM + c) =
                make_float2(acc[mf][nf][2], acc[mf][nf][3]);
        }
    }

    // ---- epilogue 2: fused score (CTA owns head h = blockIdx.x) ----
    __syncthreads();
    if (tid < 256) ssum[tid] = 0.f;
    __syncthreads();

    float sp[2][2] = {}, dp[2][2] = {};   // [mf][rowhalf]
#pragma unroll
    for (int nf = 0; nf < 4; nf++) {
        const int c = n0w + nf * 8 + (lane & 3) * 2;   // 0..127 within head
        const float a0s = sa[c],        a1s = sa[c + 1];
        const float a0d = sa[HDIM + c], a1d = sa[HDIM + c + 1];
#pragma unroll
        for (int mf = 0; mf < 2; mf++) {
            sp[mf][0] += acc[mf][nf][0] * a0s + acc[mf][nf][1] * a1s;
            sp[mf][1] += acc[mf][nf][2] * a0s + acc[mf][nf][3] * a1s;
            dp[mf][0] += acc[mf][nf][0] * a0d + acc[mf][nf][1] * a1d;
            dp[mf][1] += acc[mf][nf][2] * a0d + acc[mf][nf][3] * a1d;
        }
    }
#pragma unroll
    for (int o = 1; o <= 2; o <<= 1) {
#pragma unroll
        for (int mf = 0; mf < 2; mf++)
#pragma unroll
            for (int r = 0; r < 2; r++) {
                sp[mf][r] += __shfl_xor_sync(0xffffffffu, sp[mf][r], o);
                dp[mf][r] += __shfl_xor_sync(0xffffffffu, dp[mf][r], o);
            }
    }
    if ((lane & 3) == 0) {
#pragma unroll
        for (int mf = 0; mf < 2; mf++)
#pragma unroll
            for (int r = 0; r < 2; r++) {
                const int rt = m0w + mf * 16 + (lane >> 2) + r * 8;
                atomicAdd(&ssum[rt], sp[mf][r]);
                atomicAdd(&ssum[128 + rt], dp[mf][r]);
            }
    }
    __syncthreads();
    if (tid < 128) {
        const int h = blockIdx.x;
        g_ssrc[(bm + tid) * NHEADS + h] = ssum[tid];
        g_sdst[(bm + tid) * NHEADS + h] = ssum[128 + tid];
    }
}

// ---------------------------------------------------------------------------
// Top-16 (single kernel, smem candidates). Lexicographic (val desc, idx asc)
// — matches jax.lax.top_k. MAXC=192 keeps smem small.
// ---------------------------------------------------------------------------
__device__ __forceinline__ void insert16(float (&vals)[TOPK], int (&idxs)[TOPK],
                                         float v, int j) {
    if (v > vals[TOPK - 1] || (v == vals[TOPK - 1] && j < idxs[TOPK - 1])) {
        float pv = FLT_MAX;
        int   pi = -1;
#pragma unroll
        for (int s = 0; s < TOPK; s++) {
            float cv = vals[s];
            int   ci = idxs[s];
            bool gp = (v > pv) || (v == pv && j < pi);
            bool gc = (v > cv) || (v == cv && j < ci);
            vals[s] = gp ? pv : (gc ? v : cv);
            idxs[s] = gp ? pi : (gc ? j : ci);
            pv = cv; pi = ci;
        }
    }
}

__global__ __launch_bounds__(128) void topk_kernel(const float* __restrict__ adj) {
    __shared__ int   scnt[4];
    __shared__ float scv[4][MAXC];
    __shared__ int   sci[4][MAXC];

    const int w    = threadIdx.x >> 5;
    const int lane = threadIdx.x & 31;
    const int row  = blockIdx.x * 4 + w;
    const float4* r4 = reinterpret_cast<const float4*>(adj + (size_t)row * N_NODES);

    if (lane == 0) scnt[w] = 0;
    __syncwarp();

#pragma unroll 1
    for (int base = 0; base < N_NODES / 4; base += 128) {
        float4 v0 = r4[base + lane];
        float4 v1 = r4[base + lane + 32];
        float4 v2 = r4[base + lane + 64];
        float4 v3 = r4[base + lane + 96];
#pragma unroll
        for (int q = 0; q < 4; q++) {
            float4 v = (q == 0) ? v0 : (q == 1) ? v1 : (q == 2) ? v2 : v3;
            const int j0 = (base + lane + q * 32) * 4;
            float mx = fmaxf(fmaxf(v.x, v.y), fmaxf(v.z, v.w));
            if (mx >= THRESH) {
                if (v.x >= THRESH) { int p = atomicAdd(&scnt[w], 1); if (p < MAXC) { scv[w][p] = v.x; sci[w][p] = j0 + 0; } }
                if (v.y >= THRESH) { int p = atomicAdd(&scnt[w], 1); if (p < MAXC) { scv[w][p] = v.y; sci[w][p] = j0 + 1; } }
                if (v.z >= THRESH) { int p = atomicAdd(&scnt[w], 1); if (p < MAXC) { scv[w][p] = v.z; sci[w][p] = j0 + 2; } }
                if (v.w >= THRESH) { int p = atomicAdd(&scnt[w], 1); if (p < MAXC) { scv[w][p] = v.w; sci[w][p] = j0 + 3; } }
            }
        }
    }
    __syncwarp();
    const int c = scnt[w];

    float vals[TOPK];
    int   idxs[TOPK];
#pragma unroll
    for (int i = 0; i < TOPK; i++) { vals[i] = -FLT_MAX; idxs[i] = 0x7fffffff; }

    if (c >= TOPK && c <= MAXC) {
        for (int t = lane; t < c; t += 32)
            insert16(vals, idxs, scv[w][t], sci[w][t]);
    } else {
        // fallback: exact full scan (arbitrary data safety)
        for (int jj = lane; jj < N_NODES / 4; jj += 32) {
            float4 v = r4[jj];
            const int j0 = jj * 4;
            insert16(vals, idxs, v.x, j0 + 0);
            insert16(vals, idxs, v.y, j0 + 1);
            insert16(vals, idxs, v.z, j0 + 2);
            insert16(vals, idxs, v.w, j0 + 3);
        }
    }

#pragma unroll 1
    for (int t = 0; t < TOPK; t++) {
        float bv = vals[0];
        int   bi = idxs[0];
#pragma unroll
        for (int o = 16; o; o >>= 1) {
            float ov = __shfl_xor_sync(0xffffffffu, bv, o);
            int   oi = __shfl_xor_sync(0xffffffffu, bi, o);
            if (ov > bv || (ov == bv && oi < bi)) { bv = ov; bi = oi; }
        }
        const bool win = (idxs[0] == bi) && (vals[0] == bv);
        if (win) {
#pragma unroll
            for (int s = 0; s < TOPK - 1; s++) {
                vals[s] = vals[s + 1];
                idxs[s] = idxs[s + 1];
            }
            vals[TOPK - 1] = -FLT_MAX;
            idxs[TOPK - 1] = 0x7fffffff;
        }
        if (lane == 0) g_topk[row * TOPK + t] = bi;
    }
}

// ---------------------------------------------------------------------------
// Aggregate: PARALLEL softmax + gathered weighted Wh sum + ELU.
// ---------------------------------------------------------------------------
__global__ __launch_bounds__(128) void aggregate_kernel(float* __restrict__ out) {
    const int i   = blockIdx.x;
    const int tid = threadIdx.x;

    __shared__ int   sidx[TOPK];
    __shared__ float salpha[TOPK][NHEADS];

    if (tid < TOPK) sidx[tid] = g_topk[i * TOPK + tid];
    __syncthreads();

    if (tid < TOPK * NHEADS) {
        const int t = tid & 15, h = tid >> 4;
        float e = g_ssrc[i * NHEADS + h] + g_sdst[sidx[t] * NHEADS + h];
        e = (e >= 0.f) ? e : NEG_SLOPE * e;
        float m = e;
#pragma unroll
        for (int o = 8; o; o >>= 1) m = fmaxf(m, __shfl_xor_sync(0xffffffffu, m, o));
        float ex = expf(e - m);
        float s = ex;
#pragma unroll
        for (int o = 8; o; o >>= 1) s += __shfl_xor_sync(0xffffffffu, s, o);
        salpha[t][h] = ex / s;
    }
    __syncthreads();

    const int f = tid;
    const int h = f >> 5;
    float4 acc = make_float4(0.f, 0.f, 0.f, 0.f);
#pragma unroll
    for (int t = 0; t < TOPK; t++) {
        const float4* p = reinterpret_cast<const float4*>(g_Wh + (size_t)sidx[t] * OUT_DIM);
        float4 wv = p[f];
        float al = salpha[t][h];
        acc.x += al * wv.x; acc.y += al * wv.y;
        acc.z += al * wv.z; acc.w += al * wv.w;
    }
    float4 r;
    r.x = (acc.x > 0.f) ? acc.x : expm1f(acc.x);
    r.y = (acc.y > 0.f) ? acc.y : expm1f(acc.y);
    r.z = (acc.z > 0.f) ? acc.z : expm1f(acc.z);
    r.w = (acc.w > 0.f) ? acc.w : expm1f(acc.w);
    reinterpret_cast<float4*>(out + (size_t)i * OUT_DIM)[f] = r;
}

// ---------------------------------------------------------------------------
// Launch: topk alone on the side stream; main stream: merged conv ->
// gemm(+score) -> aggregate (waits on topk).
// ---------------------------------------------------------------------------
extern "C" void kernel_launch(void* const* d_in, const int* in_sizes, int n_in,
                              void* d_out, int out_size) {
    const float* x   = (const float*)d_in[0];
    const float* adj = (const float*)d_in[1];
    const float* W   = (const float*)d_in[2];
    const float* a   = (const float*)d_in[3];
    float* out = (float*)d_out;

    static cudaStream_t s2 = nullptr;
    static cudaEvent_t ev_fork = nullptr, ev_topk = nullptr;
    if (s2 == nullptr) {
        cudaStreamCreateWithFlags(&s2, cudaStreamNonBlocking);
        cudaEventCreateWithFlags(&ev_fork, cudaEventDisableTiming);
        cudaEventCreateWithFlags(&ev_topk, cudaEventDisableTiming);
        cudaFuncSetAttribute(hmma_gemm_kernel,
                             cudaFuncAttributeMaxDynamicSharedMemorySize, SMEM_DYN);
    }

    cudaEventRecord(ev_fork, 0);
    cudaStreamWaitEvent(s2, ev_fork, 0);

    topk_kernel<<<N_NODES / 4, 128, 0, s2>>>(adj);
    cudaEventRecord(ev_topk, s2);

    conv_xw_kernel<<<4608, 256>>>(x, W);
    hmma_gemm_kernel<<<dim3(OUT_DIM / 128, N_NODES / 128), 512, SMEM_DYN>>>(a);
    cudaStreamWaitEvent(0, ev_topk, 0);
    aggregate_kernel<<<N_NODES, 128>>>(out);
}